// round 3
// baseline (speedup 1.0000x reference)
#include <cuda_runtime.h>

// Problem constants (fixed by reference)
#define BS   1024
#define NSEQ 32
#define NBOX 128
#define NCTX 5
#define MAXC 4

// One warp per (batch, row). Fully parallel (children always have larger
// indices than parents; parents ascend & are unique per batch, so every read
// in the sequential reference sees the ORIGINAL ent_attn).
//
// Reduction is vectorized: lane l owns boxes [4l, 4l+4) and reads the
// spo/roi rows as 5 float4s each (contiguous 80B per lane => warp reads the
// full 2560B row as coalesced LDG.128).
__global__ __launch_bounds__(256) void topdown_prop_kernel(
    const float* __restrict__ ent,   // [BS,NSEQ,NBOX]
    const float* __restrict__ spo,   // [BS,NSEQ,NBOX,NCTX]
    const int*   __restrict__ ctx,   // [BS,NSEQ,NBOX,NCTX]
    const float* __restrict__ roi,   // [BS,NSEQ,NBOX,NCTX]
    const int*   __restrict__ rcls,  // [BS,NBOX]
    const float* __restrict__ w,     // [BS,NSEQ,NBOX]
    const int*   __restrict__ pidx,  // [L,BS]
    const float* __restrict__ pval,  // [L,BS]
    const int*   __restrict__ cidx,  // [L,BS,MAXC]
    const float* __restrict__ cval,  // [L,BS,MAXC]
    const int*   __restrict__ eidx,  // [L,BS,MAXC]
    const int*   __restrict__ fsmp,  // [L,BS]
    const int*   __restrict__ fslt,  // [L,BS]
    float*       __restrict__ out,   // [BS,NSEQ,NBOX]
    int L)
{
    const int warp = (blockIdx.x * blockDim.x + threadIdx.x) >> 5;
    const int lane = threadIdx.x & 31;
    if (warp >= BS * NSEQ) return;
    const int b = warp >> 5;          // / NSEQ
    const int r = warp & (NSEQ - 1);  // % NSEQ

    // --- find the iteration (if any) at which row r is a valid parent ---
    int myit = -1;
    {
        int   p = -1;
        float v = 0.f;
        if (lane < L) {
            p = pidx[lane * BS + b];
            v = pval[lane * BS + b];
        }
        unsigned m = __ballot_sync(0xffffffffu, (lane < L) && (v > 0.f) && (p == r));
        if (m) myit = __ffs(m) - 1;
    }

    const float4* row_in  = (const float4*)(ent + ((size_t)b * NSEQ + r) * NBOX);
    float4*       row_out = (float4*)(out + ((size_t)b * NSEQ + r) * NBOX);

    if (myit < 0) {
        // plain copy (128 floats = 32 lanes x float4)
        row_out[lane] = row_in[lane];
        return;
    }

    const int it   = myit;
    const int base = it * BS + b;
    const int   c0  = cidx[base * MAXC + 0];
    const float cv0 = cval[base * MAXC + 0];
    const int   e0  = eidx[base * MAXC + 0];
    const int   fs  = fsmp[base];
    const int   fl  = fslt[base];
    const int   fe  = eidx[(it * BS + fs) * MAXC + fl];

    // row pointers
    const float4* entcv = (const float4*)(ent  + ((size_t)b * NSEQ + c0) * NBOX);
    const float4* spov  = (const float4*)(spo  + ((size_t)b * NSEQ + e0) * NBOX * NCTX) + lane * 5;
    const float4* roiv  = (const float4*)(roi  + ((size_t)b * NSEQ + e0) * NBOX * NCTX) + lane * 5;
    const int4*   clsv  = (const int4*)  (rcls + (size_t)b * NBOX);

    // lane l owns boxes 4l..4l+3
    const float4 ecv = entcv[lane];
    const int4   cl  = clsv[lane];
    float ca[4];
    ca[0] = (cl.x == -1) ? 0.f : ecv.x;
    ca[1] = (cl.y == -1) ? 0.f : ecv.y;
    ca[2] = (cl.z == -1) ? 0.f : ecv.z;
    ca[3] = (cl.w == -1) ? 0.f : ecv.w;

    // issue all 10 wide loads up front for MLP
    float4 sv[5], mv[5];
    #pragma unroll
    for (int j = 0; j < 5; j++) sv[j] = spov[j];
    #pragma unroll
    for (int j = 0; j < 5; j++) mv[j] = roiv[j];

    // element e (0..19): box = e/5 (local), k = e%5. All compile-time.
    float t[NCTX] = {0.f, 0.f, 0.f, 0.f, 0.f};
    #pragma unroll
    for (int j = 0; j < 5; j++) {
        const int e = 4 * j;
        t[(e + 0) % 5] += ca[(e + 0) / 5] * sv[j].x * mv[j].x;
        t[(e + 1) % 5] += ca[(e + 1) / 5] * sv[j].y * mv[j].y;
        t[(e + 2) % 5] += ca[(e + 2) / 5] * sv[j].z * mv[j].z;
        t[(e + 3) % 5] += ca[(e + 3) / 5] * sv[j].w * mv[j].w;
    }

    #pragma unroll
    for (int o = 16; o > 0; o >>= 1) {
        t[0] += __shfl_xor_sync(0xffffffffu, t[0], o);
        t[1] += __shfl_xor_sync(0xffffffffu, t[1], o);
        t[2] += __shfl_xor_sync(0xffffffffu, t[2], o);
        t[3] += __shfl_xor_sync(0xffffffffu, t[3], o);
        t[4] += __shfl_xor_sync(0xffffffffu, t[4], o);
    }
    float tr[NCTX];
    #pragma unroll
    for (int k = 0; k < NCTX; k++) tr[k] = cv0 * t[k] + 1e-6f;

    // scatter columns: ctx_idx_adjusted[fs, fe, box=0, k]
    int cols[NCTX];
    const int* cbase = ctx + (((size_t)fs * NSEQ + fe) * NBOX) * NCTX;
    #pragma unroll
    for (int k = 0; k < NCTX; k++) cols[k] = cbase[k];

    // --- row update: lane owns boxes 4l..4l+3 (cls int4 reused from above) ---
    const float4 sub = row_in[lane];
    const float4 wv  = ((const float4*)(w + ((size_t)b * NSEQ + r) * NBOX))[lane];

    float su[4]  = {sub.x, sub.y, sub.z, sub.w};
    float wa[4]  = {wv.x, wv.y, wv.z, wv.w};
    int   cla[4] = {cl.x, cl.y, cl.z, cl.w};

    float u[4];
    float mx = 0.f;
    #pragma unroll
    for (int q = 0; q < 4; q++) {
        const int box = lane * 4 + q;
        float add = 1e-6f;
        #pragma unroll
        for (int k = 0; k < NCTX; k++)
            if (cols[k] == box) add = tr[k];
        u[q] = su[q] + add * wa[q];
        mx = fmaxf(mx, fabsf(u[q]));
    }
    #pragma unroll
    for (int o = 16; o > 0; o >>= 1)
        mx = fmaxf(mx, __shfl_xor_sync(0xffffffffu, mx, o));
    const float d = (mx <= 1.f) ? 1.f : mx;

    float rr[4];
    #pragma unroll
    for (int q = 0; q < 4; q++) {
        float v = u[q] / d;
        if (cla[q] == -1) v = -1.0f;
        rr[q] = v;
    }
    float4 res;
    res.x = rr[0]; res.y = rr[1]; res.z = rr[2]; res.w = rr[3];
    row_out[lane] = res;
}

extern "C" void kernel_launch(void* const* d_in, const int* in_sizes, int n_in,
                              void* d_out, int out_size) {
    const float* ent  = (const float*)d_in[0];   // ent_attn
    const float* spo  = (const float*)d_in[1];   // spo_attn
    const int*   ctx  = (const int*)  d_in[2];   // ctx_idx_adjusted
    const float* roi  = (const float*)d_in[3];   // roi_mask
    const int*   rcls = (const int*)  d_in[4];   // roi_cls
    const float* w    = (const float*)d_in[5];   // weight_on_children
    const int*   pidx = (const int*)  d_in[6];   // parent_idx [L,BS]
    const float* pval = (const float*)d_in[7];   // parent_valid
    const int*   cidx = (const int*)  d_in[8];   // child_idx
    const float* cval = (const float*)d_in[9];   // child_valid
    const int*   eidx = (const int*)  d_in[10];  // edge_idx
    const int*   fsmp = (const int*)  d_in[11];  // flat_sample
    const int*   fslt = (const int*)  d_in[12];  // flat_slot

    const int L = in_sizes[6] / BS;

    const int total_warps = BS * NSEQ;              // 32768
    const int threads = 256;                        // 8 warps/block
    const int blocks = (total_warps * 32 + threads - 1) / threads;  // 4096

    topdown_prop_kernel<<<blocks, threads>>>(
        ent, spo, ctx, roi, rcls, w,
        pidx, pval, cidx, cval, eidx, fsmp, fslt,
        (float*)d_out, L);
}

// round 5
// speedup vs baseline: 1.0353x; 1.0353x over previous
#include <cuda_runtime.h>

// Problem constants (fixed by reference)
#define BS   1024
#define NSEQ 32
#define NBOX 128
#define NCTX 5
#define MAXC 4

// Phase 1: cudaMemcpyAsync D2D copies ent -> out (all rows).
// Phase 2: this kernel, one warp per (it, b) task, overwrites only the
// parent rows (pval>0). Fully parallel: children always have larger indices
// than parents and parents ascend & are unique per batch, so every read in
// the sequential reference sees the ORIGINAL ent_attn. Reads come from `ent`
// (untouched), writes go to `out`; the only hazard vs the memcpy is
// write-after-write on parent rows, ordered by the stream.
__global__ __launch_bounds__(256) void topdown_compute_kernel(
    const float* __restrict__ ent,   // [BS,NSEQ,NBOX]
    const float* __restrict__ spo,   // [BS,NSEQ,NBOX,NCTX]
    const int*   __restrict__ ctx,   // [BS,NSEQ,NBOX,NCTX]
    const float* __restrict__ roi,   // [BS,NSEQ,NBOX,NCTX]
    const int*   __restrict__ rcls,  // [BS,NBOX]
    const float* __restrict__ w,     // [BS,NSEQ,NBOX]
    const int*   __restrict__ pidx,  // [L,BS]
    const float* __restrict__ pval,  // [L,BS]
    const int*   __restrict__ cidx,  // [L,BS,MAXC]
    const float* __restrict__ cval,  // [L,BS,MAXC]
    const int*   __restrict__ eidx,  // [L,BS,MAXC]
    const int*   __restrict__ fsmp,  // [L,BS]
    const int*   __restrict__ fslt,  // [L,BS]
    float*       __restrict__ out,   // [BS,NSEQ,NBOX]
    int n_tasks)
{
    const int task = (blockIdx.x * blockDim.x + threadIdx.x) >> 5;
    const int lane = threadIdx.x & 31;
    if (task >= n_tasks) return;
    // consecutive warps -> consecutive b (same it): index loads coalesce
    const int it = task >> 10;          // / BS
    const int b  = task & (BS - 1);     // % BS

    const int base = it * BS + b;
    const float pv = pval[base];
    if (pv <= 0.f) return;
    const int r = pidx[base];

    const int   c0  = cidx[base * MAXC + 0];
    const float cv0 = cval[base * MAXC + 0];
    const int   e0  = eidx[base * MAXC + 0];
    const int   fs  = fsmp[base];
    const int   fl  = fslt[base];
    const int   fe  = eidx[(it * BS + fs) * MAXC + fl];

    // --- transfer[k] = cv0 * sum_box ent[b,c0,box]*cls*spo[b,e0,box,k]*roi[b,e0,box,k] + 1e-6 ---
    const float* entc   = ent  + ((size_t)b * NSEQ + c0) * NBOX;
    const float* spor   = spo  + ((size_t)b * NSEQ + e0) * NBOX * NCTX;
    const float* roir   = roi  + ((size_t)b * NSEQ + e0) * NBOX * NCTX;
    const int*   clsrow = rcls + (size_t)b * NBOX;

    float t0 = 0.f, t1 = 0.f, t2 = 0.f, t3 = 0.f, t4 = 0.f;
    #pragma unroll
    for (int q = 0; q < NBOX / 32; q++) {
        const int box = lane + q * 32;
        float ca = entc[box];
        if (clsrow[box] == -1) ca = 0.f;
        const float* s  = spor + box * NCTX;
        const float* mr = roir + box * NCTX;
        t0 += ca * s[0] * mr[0];
        t1 += ca * s[1] * mr[1];
        t2 += ca * s[2] * mr[2];
        t3 += ca * s[3] * mr[3];
        t4 += ca * s[4] * mr[4];
    }
    #pragma unroll
    for (int o = 16; o > 0; o >>= 1) {
        t0 += __shfl_xor_sync(0xffffffffu, t0, o);
        t1 += __shfl_xor_sync(0xffffffffu, t1, o);
        t2 += __shfl_xor_sync(0xffffffffu, t2, o);
        t3 += __shfl_xor_sync(0xffffffffu, t3, o);
        t4 += __shfl_xor_sync(0xffffffffu, t4, o);
    }
    float tr[NCTX];
    tr[0] = cv0 * t0 + 1e-6f;
    tr[1] = cv0 * t1 + 1e-6f;
    tr[2] = cv0 * t2 + 1e-6f;
    tr[3] = cv0 * t3 + 1e-6f;
    tr[4] = cv0 * t4 + 1e-6f;

    // scatter columns: ctx_idx_adjusted[fs, fe, box=0, k]
    int cols[NCTX];
    const int* cbase = ctx + (((size_t)fs * NSEQ + fe) * NBOX) * NCTX;
    #pragma unroll
    for (int k = 0; k < NCTX; k++) cols[k] = cbase[k];

    // --- row update: each lane owns 4 consecutive boxes of the parent row ---
    const float4 sub = ((const float4*)(ent + ((size_t)b * NSEQ + r) * NBOX))[lane];
    const float4 wv  = ((const float4*)(w   + ((size_t)b * NSEQ + r) * NBOX))[lane];
    const int4   cl  = ((const int4*)clsrow)[lane];

    float su[4]  = {sub.x, sub.y, sub.z, sub.w};
    float wa[4]  = {wv.x, wv.y, wv.z, wv.w};
    int   cla[4] = {cl.x, cl.y, cl.z, cl.w};

    float u[4];
    float mx = 0.f;
    #pragma unroll
    for (int q = 0; q < 4; q++) {
        const int box = lane * 4 + q;
        float add = 1e-6f;
        #pragma unroll
        for (int k = 0; k < NCTX; k++)
            if (cols[k] == box) add = tr[k];
        u[q] = su[q] + add * wa[q];
        mx = fmaxf(mx, fabsf(u[q]));
    }
    #pragma unroll
    for (int o = 16; o > 0; o >>= 1)
        mx = fmaxf(mx, __shfl_xor_sync(0xffffffffu, mx, o));
    const float d = (mx <= 1.f) ? 1.f : mx;

    float rr[4];
    #pragma unroll
    for (int q = 0; q < 4; q++) {
        float v = u[q] / d;
        if (cla[q] == -1) v = -1.0f;
        rr[q] = v;
    }
    float4 res;
    res.x = rr[0]; res.y = rr[1]; res.z = rr[2]; res.w = rr[3];
    ((float4*)(out + ((size_t)b * NSEQ + r) * NBOX))[lane] = res;
}

extern "C" void kernel_launch(void* const* d_in, const int* in_sizes, int n_in,
                              void* d_out, int out_size) {
    const float* ent  = (const float*)d_in[0];   // ent_attn
    const float* spo  = (const float*)d_in[1];   // spo_attn
    const int*   ctx  = (const int*)  d_in[2];   // ctx_idx_adjusted
    const float* roi  = (const float*)d_in[3];   // roi_mask
    const int*   rcls = (const int*)  d_in[4];   // roi_cls
    const float* w    = (const float*)d_in[5];   // weight_on_children
    const int*   pidx = (const int*)  d_in[6];   // parent_idx [L,BS]
    const float* pval = (const float*)d_in[7];   // parent_valid
    const int*   cidx = (const int*)  d_in[8];   // child_idx
    const float* cval = (const float*)d_in[9];   // child_valid
    const int*   eidx = (const int*)  d_in[10];  // edge_idx
    const int*   fsmp = (const int*)  d_in[11];  // flat_sample
    const int*   fslt = (const int*)  d_in[12];  // flat_slot

    const int L = in_sizes[6] / BS;
    const int n_tasks = L * BS;

    // Phase 1: bulk copy ent -> out (async D2D, capture-legal)
    cudaMemcpyAsync(d_out, ent, (size_t)BS * NSEQ * NBOX * sizeof(float),
                    cudaMemcpyDeviceToDevice, 0);

    // Phase 2: compute parent-row updates (overwrites copied rows)
    const int threads = 256;                                  // 8 warps/block
    const int blocks = (n_tasks * 32 + threads - 1) / threads;
    topdown_compute_kernel<<<blocks, threads>>>(
        ent, spo, ctx, roi, rcls, w,
        pidx, pval, cidx, cval, eidx, fsmp, fslt,
        (float*)d_out, n_tasks);
}

// round 8
// speedup vs baseline: 1.1931x; 1.1523x over previous
#include <cuda_runtime.h>

// Problem constants (fixed by reference)
#define BS   1024
#define NSEQ 32
#define NBOX 128
#define NCTX 5
#define MAXC 4

// Single fused kernel.
//  - Warps [0, n_tasks): one per (it,b) task; if pval>0, compute the updated
//    parent row and write it to out.
//  - Warps [n_tasks, n_tasks + BS*NSEQ): one per (b,r) row; if r is NOT a
//    valid parent in any iteration, copy ent row -> out row. (Parent rows are
//    written exclusively by compute warps; each out row written exactly once.)
// Fully parallel: children always have larger indices than parents; parents
// ascend & are unique per batch, so every read in the sequential reference
// sees the ORIGINAL ent_attn.
// Streaming data (spo/roi rows, copy rows, outputs) uses .cs hints to keep
// L1 for the reused index/cls/ent data.
__global__ __launch_bounds__(256) void topdown_fused_kernel(
    const float* __restrict__ ent,   // [BS,NSEQ,NBOX]
    const float* __restrict__ spo,   // [BS,NSEQ,NBOX,NCTX]
    const int*   __restrict__ ctx,   // [BS,NSEQ,NBOX,NCTX]
    const float* __restrict__ roi,   // [BS,NSEQ,NBOX,NCTX]
    const int*   __restrict__ rcls,  // [BS,NBOX]
    const float* __restrict__ w,     // [BS,NSEQ,NBOX]
    const int*   __restrict__ pidx,  // [L,BS]
    const float* __restrict__ pval,  // [L,BS]
    const int*   __restrict__ cidx,  // [L,BS,MAXC]
    const float* __restrict__ cval,  // [L,BS,MAXC]
    const int*   __restrict__ eidx,  // [L,BS,MAXC]
    const int*   __restrict__ fsmp,  // [L,BS]
    const int*   __restrict__ fslt,  // [L,BS]
    float*       __restrict__ out,   // [BS,NSEQ,NBOX]
    int n_tasks, int L)
{
    const int gwarp = (blockIdx.x * blockDim.x + threadIdx.x) >> 5;
    const int lane  = threadIdx.x & 31;

    if (gwarp >= n_tasks) {
        // ---------------- copy warp: one per (b, r) row ----------------
        const int idx = gwarp - n_tasks;
        if (idx >= BS * NSEQ) return;
        const int b = idx >> 5;          // / NSEQ
        const int r = idx & (NSEQ - 1);  // % NSEQ

        // is row r a valid parent at any iteration? (L <= 32)
        int   p = -1;
        float v = 0.f;
        if (lane < L) {
            p = pidx[lane * BS + b];
            v = pval[lane * BS + b];
        }
        const unsigned m =
            __ballot_sync(0xffffffffu, (lane < L) && (v > 0.f) && (p == r));
        if (m) return;  // compute warp owns this row

        const float4* src = (const float4*)(ent + ((size_t)b * NSEQ + r) * NBOX);
        float4*       dst = (float4*)(out + ((size_t)b * NSEQ + r) * NBOX);
        const float4 val = __ldcs(src + lane);
        __stcs(dst + lane, val);
        return;
    }

    // ---------------- compute warp: one per (it, b) task ----------------
    const int task = gwarp;
    const int it = task >> 10;          // / BS
    const int b  = task & (BS - 1);     // % BS

    const int base = it * BS + b;
    const float pv = pval[base];
    if (pv <= 0.f) return;
    const int r = pidx[base];

    const int   c0  = cidx[base * MAXC + 0];
    const float cv0 = cval[base * MAXC + 0];
    const int   e0  = eidx[base * MAXC + 0];
    const int   fs  = fsmp[base];
    const int   fl  = fslt[base];
    const int   fe  = eidx[(it * BS + fs) * MAXC + fl];

    // --- transfer[k] = cv0 * sum_box ent[b,c0,box]*cls*spo[b,e0,box,k]*roi[b,e0,box,k] + 1e-6 ---
    const float* entc   = ent  + ((size_t)b * NSEQ + c0) * NBOX;
    const float* spor   = spo  + ((size_t)b * NSEQ + e0) * NBOX * NCTX;
    const float* roir   = roi  + ((size_t)b * NSEQ + e0) * NBOX * NCTX;
    const int*   clsrow = rcls + (size_t)b * NBOX;

    float t0 = 0.f, t1 = 0.f, t2 = 0.f, t3 = 0.f, t4 = 0.f;
    #pragma unroll
    for (int q = 0; q < NBOX / 32; q++) {
        const int box = lane + q * 32;
        float ca = entc[box];
        if (clsrow[box] == -1) ca = 0.f;
        const float* s  = spor + box * NCTX;
        const float* mr = roir + box * NCTX;
        t0 += ca * __ldcs(s + 0) * __ldcs(mr + 0);
        t1 += ca * __ldcs(s + 1) * __ldcs(mr + 1);
        t2 += ca * __ldcs(s + 2) * __ldcs(mr + 2);
        t3 += ca * __ldcs(s + 3) * __ldcs(mr + 3);
        t4 += ca * __ldcs(s + 4) * __ldcs(mr + 4);
    }
    #pragma unroll
    for (int o = 16; o > 0; o >>= 1) {
        t0 += __shfl_xor_sync(0xffffffffu, t0, o);
        t1 += __shfl_xor_sync(0xffffffffu, t1, o);
        t2 += __shfl_xor_sync(0xffffffffu, t2, o);
        t3 += __shfl_xor_sync(0xffffffffu, t3, o);
        t4 += __shfl_xor_sync(0xffffffffu, t4, o);
    }
    float tr[NCTX];
    tr[0] = cv0 * t0 + 1e-6f;
    tr[1] = cv0 * t1 + 1e-6f;
    tr[2] = cv0 * t2 + 1e-6f;
    tr[3] = cv0 * t3 + 1e-6f;
    tr[4] = cv0 * t4 + 1e-6f;

    // scatter columns: ctx_idx_adjusted[fs, fe, box=0, k] (uniform loads)
    int cols[NCTX];
    const int* cbase = ctx + (((size_t)fs * NSEQ + fe) * NBOX) * NCTX;
    #pragma unroll
    for (int k = 0; k < NCTX; k++) cols[k] = cbase[k];

    // --- row update: each lane owns 4 consecutive boxes of the parent row ---
    const float4 sub = ((const float4*)(ent + ((size_t)b * NSEQ + r) * NBOX))[lane];
    const float4 wv  = __ldcs(((const float4*)(w + ((size_t)b * NSEQ + r) * NBOX)) + lane);
    const int4   cl  = ((const int4*)clsrow)[lane];

    float su[4]  = {sub.x, sub.y, sub.z, sub.w};
    float wa[4]  = {wv.x, wv.y, wv.z, wv.w};
    int   cla[4] = {cl.x, cl.y, cl.z, cl.w};

    float u[4];
    float mx = 0.f;
    #pragma unroll
    for (int q = 0; q < 4; q++) {
        const int box = lane * 4 + q;
        float add = 1e-6f;
        #pragma unroll
        for (int k = 0; k < NCTX; k++)
            if (cols[k] == box) add = tr[k];
        u[q] = su[q] + add * wa[q];
        mx = fmaxf(mx, fabsf(u[q]));
    }
    #pragma unroll
    for (int o = 16; o > 0; o >>= 1)
        mx = fmaxf(mx, __shfl_xor_sync(0xffffffffu, mx, o));
    const float d = (mx <= 1.f) ? 1.f : mx;

    float rr[4];
    #pragma unroll
    for (int q = 0; q < 4; q++) {
        float vvv = u[q] / d;
        if (cla[q] == -1) vvv = -1.0f;
        rr[q] = vvv;
    }
    float4 res;
    res.x = rr[0]; res.y = rr[1]; res.z = rr[2]; res.w = rr[3];
    __stcs(((float4*)(out + ((size_t)b * NSEQ + r) * NBOX)) + lane, res);
}

extern "C" void kernel_launch(void* const* d_in, const int* in_sizes, int n_in,
                              void* d_out, int out_size) {
    const float* ent  = (const float*)d_in[0];   // ent_attn
    const float* spo  = (const float*)d_in[1];   // spo_attn
    const int*   ctx  = (const int*)  d_in[2];   // ctx_idx_adjusted
    const float* roi  = (const float*)d_in[3];   // roi_mask
    const int*   rcls = (const int*)  d_in[4];   // roi_cls
    const float* w    = (const float*)d_in[5];   // weight_on_children
    const int*   pidx = (const int*)  d_in[6];   // parent_idx [L,BS]
    const float* pval = (const float*)d_in[7];   // parent_valid
    const int*   cidx = (const int*)  d_in[8];   // child_idx
    const float* cval = (const float*)d_in[9];   // child_valid
    const int*   eidx = (const int*)  d_in[10];  // edge_idx
    const int*   fsmp = (const int*)  d_in[11];  // flat_sample
    const int*   fslt = (const int*)  d_in[12];  // flat_slot

    const int L = in_sizes[6] / BS;
    const int n_tasks = L * BS;

    const int total_warps = n_tasks + BS * NSEQ;  // compute + copy warps
    const int threads = 256;                      // 8 warps/block
    const int blocks = (total_warps * 32 + threads - 1) / threads;

    topdown_fused_kernel<<<blocks, threads>>>(
        ent, spo, ctx, roi, rcls, w,
        pidx, pval, cidx, cval, eidx, fsmp, fslt,
        (float*)d_out, n_tasks, L);
}